// round 8
// baseline (speedup 1.0000x reference)
#include <cuda_runtime.h>
#include <cuda_fp16.h>
#include <math.h>
#include <stdint.h>

// ---------------------------------------------------------------------------
// SimpleVQ: B=32, H=1, L=4096, D=64, S=512
// out (f32): quantized[NVEC*64] | z[NVEC] | l_commit | errs2[NVEC]
// fp16 HFMA2 approx distance pass + certified margin + exact fp32 refine.
// ---------------------------------------------------------------------------

typedef unsigned long long ull;

#define NVEC   131072
#define NCODE  512
#define ZOFF   8388608
#define LOFF   8519680
#define EOFF   8519681
#define NBLK   148
#define NTHR   512
#define NTILE  1024

#define CBS    144             // fp16 codebook row stride bytes (64*2 + 16 pad)
#define DSTRIDE 272            // per-thread bf16 s-buffer stride (16-aligned)

// ---- smem layout (bytes) ---------------------------------------------------
#define SCB    0               // fp16 codebook [512][72]        73728
#define SDIST  73728           // bf16 s-vals, per-thread 272B  139264
#define SCN    212992          // fp32 cn/2 [512]                 2048
#define SMIN   215040          // u32 per-row approx min           512
#define SKEY   215552          // ull[128] final keys             1024
#define SRED   216576          // float[512]                      2048
#define SMEM_BYTES 218624

__device__ float  g_cbf[512 * 64];     // fp32 [s][d]
__device__ __half g_cbh[512 * 64];     // fp16 [s][d]
__device__ float  g_cn[512];
__device__ float  g_part[NBLK];

// ---- helpers ---------------------------------------------------------------
__device__ __forceinline__ uint32_t bf2(float lo, float hi) {
    uint32_t r; asm("cvt.rn.bf16x2.f32 %0, %1, %2;" : "=r"(r) : "f"(hi), "f"(lo)); return r;
}
__device__ __forceinline__ uint32_t minbf2(uint32_t a, uint32_t b) {
    uint32_t r; asm("min.bf16x2 %0, %1, %2;" : "=r"(r) : "r"(a), "r"(b)); return r;
}
__device__ __forceinline__ uint32_t enc32(float f) {
    uint32_t u = __float_as_uint(f);
    return (u & 0x80000000u) ? ~u : (u | 0x80000000u);
}
__device__ __forceinline__ float dec32(uint32_t m) {
    uint32_t u = (m & 0x80000000u) ? (m & 0x7FFFFFFFu) : ~m;
    return __uint_as_float(u);
}
__device__ __forceinline__ __half2 u2h2(uint32_t u) {
    __half2 h; *(uint32_t*)&h = u; return h;
}

// ---------------------------------------------------------------------------
// Init: codebook (double trig; identical math to all passing rounds)
// ---------------------------------------------------------------------------
__global__ void vq_init() {
    __shared__ float red[64];
    const int s = blockIdx.x;
    const int d = threadIdx.x;
    const int j = d & 31;

    double expn = -((double)(2 * j) / 64.0);
    float  il   = (float)pow(100000.0, expn);
    float  pre  = __fmul_rn((float)s, il);
    float  e    = (d < 32) ? (float)sin((double)pre) : (float)cos((double)pre);

    red[d] = __fmul_rn(e, e);
    __syncthreads();
    for (int o = 32; o > 0; o >>= 1) {
        if (d < o) red[d] = __fadd_rn(red[d], red[d + o]);
        __syncthreads();
    }
    float m = __fadd_rn(__fmul_rn(red[0], (1.0f / 64.0f)), 1e-6f);
    __syncthreads();
    float r = (float)(1.0 / sqrt((double)m));
    float c = __fmul_rn(__fmul_rn(e, r), 0.35355339059327373f);

    g_cbf[s * 64 + d] = c;
    g_cbh[s * 64 + d] = __float2half_rn(c);

    red[d] = __fmul_rn(c, c);
    __syncthreads();
    for (int o = 32; o > 0; o >>= 1) {
        if (d < o) red[d] = __fadd_rn(red[d], red[d + o]);
        __syncthreads();
    }
    if (d == 0) g_cn[s] = red[0];
}

// ---------------------------------------------------------------------------
__device__ __forceinline__ void refine(const float* __restrict__ vecs,
                                       int vglob, int row, int code,
                                       float vn, const float* schn, ull* skey) {
    const float4* vp = (const float4*)(vecs + ((size_t)vglob) * 64);
    const float4* cp = (const float4*)(g_cbf + (size_t)code * 64);
    float dot = 0.f;
#pragma unroll
    for (int kk = 0; kk < 16; kk++) {
        float4 a = vp[kk], b = cp[kk];
        dot = fmaf(a.x, b.x, dot);
        dot = fmaf(a.y, b.y, dot);
        dot = fmaf(a.z, b.z, dot);
        dot = fmaf(a.w, b.w, dot);
    }
    // cn = 2*schn exactly (schn = 0.5f*cn, both exact scalings)
    float dist = __fadd_rn(fmaf(-2.f, dot, vn), 2.f * schn[code]);
    ull key = ((ull)enc32(dist) << 9) | (uint32_t)code;
    atomicMin(&skey[row], key);
}

// ---------------------------------------------------------------------------
__global__ void __launch_bounds__(NTHR, 1) vq_main(const float* __restrict__ vecs,
                                                   const float* __restrict__ mask,
                                                   float* __restrict__ out) {
    extern __shared__ unsigned char smem[];
    float*    schn = (float*)(smem + SCN);
    uint32_t* smin = (uint32_t*)(smem + SMIN);
    ull*      skey = (ull*)(smem + SKEY);
    float*    sred = (float*)(smem + SRED);

    const int t   = threadIdx.x;
    const int row = t >> 2;
    const int seg = t & 3;

    // ---- load fp16 codebook (padded rows) + cn/2 into smem ----
    {
        const uint4* src = (const uint4*)g_cbh;       // 4096 x 16B
        for (int i = t; i < 4096; i += NTHR) {
            uint4 w = src[i];
            *(uint4*)(smem + SCB + (i >> 3) * CBS + (i & 7) * 16) = w;
        }
        for (int i = t; i < NCODE; i += NTHR) schn[i] = 0.5f * g_cn[i];
    }
    __syncthreads();

    float lacc = 0.f;

    for (int tile = blockIdx.x; tile < NTILE; tile += NBLK) {
        const int vbase = tile * 128;
        const int vglob = vbase + row;

        // ---- load row: vn (exact ascending) + fp16 conversion ----
        const float4* vp = (const float4*)(vecs + ((size_t)vglob) * 64);
        float vn = 0.f;
        __half2 va[32];
#pragma unroll
        for (int i = 0; i < 16; i++) {
            float4 x = vp[i];
            vn = __fadd_rn(vn, __fmul_rn(x.x, x.x));
            vn = __fadd_rn(vn, __fmul_rn(x.y, x.y));
            vn = __fadd_rn(vn, __fmul_rn(x.z, x.z));
            vn = __fadd_rn(vn, __fmul_rn(x.w, x.w));
            va[2 * i]     = __float22half2_rn(make_float2(x.x, x.y));
            va[2 * i + 1] = __float22half2_rn(make_float2(x.z, x.w));
        }
        // certified margin (s-units): 2*(dot_err 0.0139*sqrt(vn) + bf16 store 0.15) + slush
        const float margin = fmaf(0.035f, sqrtf(vn), 0.35f);

        if (t < 128) { smin[t] = 0xFFFFFFFFu; skey[t] = ~0ull; }
        __syncthreads();

        // ---- HFMA2 pass: this thread covers codes seg+4k, k=0..127 ----
        float localmin = 3.4e38f;
        float prevs = 0.f;
        const unsigned char* cbp = smem + SCB + seg * CBS;
        uint32_t* dbuf = (uint32_t*)(smem + SDIST + t * DSTRIDE);
#pragma unroll 2
        for (int k = 0; k < 128; k++) {
            const uint4* cq = (const uint4*)(cbp + (size_t)k * (4 * CBS));
            uint4 c0 = cq[0], c1 = cq[1], c2 = cq[2], c3 = cq[3];
            __half2 a0 = __hmul2(va[0], u2h2(c0.x));
            __half2 a1 = __hmul2(va[1], u2h2(c0.y));
            __half2 a2 = __hmul2(va[2], u2h2(c0.z));
            __half2 a3 = __hmul2(va[3], u2h2(c0.w));
            a0 = __hfma2(va[4],  u2h2(c1.x), a0);
            a1 = __hfma2(va[5],  u2h2(c1.y), a1);
            a2 = __hfma2(va[6],  u2h2(c1.z), a2);
            a3 = __hfma2(va[7],  u2h2(c1.w), a3);
            a0 = __hfma2(va[8],  u2h2(c2.x), a0);
            a1 = __hfma2(va[9],  u2h2(c2.y), a1);
            a2 = __hfma2(va[10], u2h2(c2.z), a2);
            a3 = __hfma2(va[11], u2h2(c2.w), a3);
            a0 = __hfma2(va[12], u2h2(c3.x), a0);
            a1 = __hfma2(va[13], u2h2(c3.y), a1);
            a2 = __hfma2(va[14], u2h2(c3.z), a2);
            a3 = __hfma2(va[15], u2h2(c3.w), a3);
            uint4 c4 = cq[4], c5 = cq[5], c6 = cq[6], c7 = cq[7];
            a0 = __hfma2(va[16], u2h2(c4.x), a0);
            a1 = __hfma2(va[17], u2h2(c4.y), a1);
            a2 = __hfma2(va[18], u2h2(c4.z), a2);
            a3 = __hfma2(va[19], u2h2(c4.w), a3);
            a0 = __hfma2(va[20], u2h2(c5.x), a0);
            a1 = __hfma2(va[21], u2h2(c5.y), a1);
            a2 = __hfma2(va[22], u2h2(c5.z), a2);
            a3 = __hfma2(va[23], u2h2(c5.w), a3);
            a0 = __hfma2(va[24], u2h2(c6.x), a0);
            a1 = __hfma2(va[25], u2h2(c6.y), a1);
            a2 = __hfma2(va[26], u2h2(c6.z), a2);
            a3 = __hfma2(va[27], u2h2(c6.w), a3);
            a0 = __hfma2(va[28], u2h2(c7.x), a0);
            a1 = __hfma2(va[29], u2h2(c7.y), a1);
            a2 = __hfma2(va[30], u2h2(c7.z), a2);
            a3 = __hfma2(va[31], u2h2(c7.w), a3);

            float2 f0 = __half22float2(a0);
            float2 f1 = __half22float2(a1);
            float2 f2 = __half22float2(a2);
            float2 f3 = __half22float2(a3);
            float dot = ((f0.x + f0.y) + (f1.x + f1.y))
                      + ((f2.x + f2.y) + (f3.x + f3.y));
            const int code = 4 * k + seg;
            float sva = schn[code] - dot;       // dist = vn + 2*s
            localmin = fminf(localmin, sva);
            if (k & 1) dbuf[k >> 1] = bf2(prevs, sva);
            else       prevs = sva;
        }
        atomicMin(&smin[row], enc32(localmin));
        __syncthreads();

        // ---- threshold scan + exact fp32 refine ----
        {
            const float thr = dec32(smin[row]) + margin;
            const uint4* db = (const uint4*)(smem + SDIST + t * DSTRIDE);
#pragma unroll 1
            for (int i = 0; i < 16; i++) {
                uint4 w = db[i];
                uint32_t mm = minbf2(minbf2(w.x, w.y), minbf2(w.z, w.w));
                float f1 = __uint_as_float(mm << 16);
                float f2 = __uint_as_float(mm & 0xFFFF0000u);
                if (fminf(f1, f2) < thr) {
                    uint32_t ws[4] = {w.x, w.y, w.z, w.w};
#pragma unroll
                    for (int m = 0; m < 4; m++) {
                        float flo = __uint_as_float(ws[m] << 16);
                        float fhi = __uint_as_float(ws[m] & 0xFFFF0000u);
                        if (flo < thr)
                            refine(vecs, vglob, row, 4 * (8 * i + 2 * m) + seg, vn, schn, skey);
                        if (fhi < thr)
                            refine(vecs, vglob, row, 4 * (8 * i + 2 * m + 1) + seg, vn, schn, skey);
                    }
                }
            }
        }
        __syncthreads();

        // ---- outputs ----
        if (t < 128) {
            ull key = skey[t];
            int s = (int)(key & 511);
            float dist = dec32((uint32_t)(key >> 9));
            float er = fmaxf(dist, 0.f);
            int v = vbase + t;
            out[ZOFF + v] = (float)s;
            out[EOFF + v] = er;
            lacc = __fadd_rn(lacc, __fmul_rn(mask[v], er));
        }
        {
            int s = (int)(skey[row] & 511);
            const float4* cp = (const float4*)(g_cbf + (size_t)s * 64 + seg * 16);
            float4* dst = (float4*)(out + ((size_t)vglob) * 64 + seg * 16);
            dst[0] = cp[0]; dst[1] = cp[1]; dst[2] = cp[2]; dst[3] = cp[3];
        }
        __syncthreads();
    }

    // ---- l_commit block partial ----
    sred[t] = lacc;
    __syncthreads();
    for (int o = NTHR / 2; o > 0; o >>= 1) {
        if (t < o) sred[t] = __fadd_rn(sred[t], sred[t + o]);
        __syncthreads();
    }
    if (t == 0) g_part[blockIdx.x] = sred[0];
}

// ---------------------------------------------------------------------------
__global__ void vq_final(float* __restrict__ out) {
    __shared__ float s[256];
    int t = threadIdx.x;
    s[t] = (t < NBLK) ? g_part[t] : 0.f;
    __syncthreads();
    for (int o = 128; o > 0; o >>= 1) {
        if (t < o) s[t] = __fadd_rn(s[t], s[t + o]);
        __syncthreads();
    }
    if (t == 0) out[LOFF] = __fmul_rn(s[0], (1.0f / 131072.0f));
}

// ---------------------------------------------------------------------------
extern "C" void kernel_launch(void* const* d_in, const int* in_sizes, int n_in,
                              void* d_out, int out_size) {
    (void)in_sizes; (void)n_in; (void)out_size;
    const float* vecs = (const float*)d_in[0];
    const float* mask = (const float*)d_in[1];
    float* out = (float*)d_out;

    cudaFuncSetAttribute(vq_main, cudaFuncAttributeMaxDynamicSharedMemorySize, SMEM_BYTES);

    vq_init<<<NCODE, 64>>>();
    vq_main<<<NBLK, NTHR, SMEM_BYTES>>>(vecs, mask, out);
    vq_final<<<1, 256>>>(out);
}

// round 9
// speedup vs baseline: 1.0613x; 1.0613x over previous
#include <cuda_runtime.h>
#include <math.h>
#include <stdint.h>

// ---------------------------------------------------------------------------
// SimpleVQ: B=32, H=1, L=4096, D=64, S=512
// out (f32): quantized[NVEC*64] | z[NVEC] | l_commit | errs2[NVEC]
// Exact-head (24 dims) + certified degree-8 Chebyshev tail approx (9 MACs)
// fp32 scan  ->  measured-margin refine (exact fp32)  ->  outputs.
// ---------------------------------------------------------------------------

typedef unsigned long long ull;

#define NVEC   131072
#define NCODE  512
#define ZOFF   8388608
#define LOFF   8519680
#define EOFF   8519681
#define NBLK   148
#define NTHR   512
#define NTILE  1024

#define JHEAD  12              // exact head dims per trig (24 total)
#define NSEQ   40              // (32-JHEAD)*2 tail sequences
#define HTS    28              // head table row stride (floats): 24 data + 4 pad
#define PTS    12              // poly table row stride (floats): 9 T_k + cn + 2 pad
#define DSTRIDE 272            // per-thread bf16 w-buffer stride (bytes)

// ---- smem layout (bytes) ---------------------------------------------------
#define SHT    0               // head table [512][28] f32     57344
#define SPT    57344           // poly table [512][12] f32     24576
#define SDIST  81920           // bf16 w-vals, 512 thr x 272  139264
#define SMIN   221184          // u32 per-row approx min         512
#define SKEY   221696          // ull[128] final keys           1024
#define SRED   222720          // float[512]                    2048
#define SMEM_BYTES 224768

__device__ float g_cbf[512 * 64];    // fp32 codebook [s][d]
__device__ float g_cn[512];
__device__ float g_rt[512];          // r~_s = r_s * 64^-0.25
__device__ float g_HT[512 * HTS];    // head table
__device__ float g_PT[512 * PTS];    // scaled Chebyshev table + cn
__device__ float g_cf[NSEQ * 9];     // tail fit coefficients (unscaled)
__device__ float g_E[NSEQ];          // certified per-seq max error * r~max
__device__ float g_part[NBLK];

// ---- helpers ---------------------------------------------------------------
__device__ __forceinline__ uint32_t bf2(float lo, float hi) {
    uint32_t r; asm("cvt.rn.bf16x2.f32 %0, %1, %2;" : "=r"(r) : "f"(hi), "f"(lo)); return r;
}
__device__ __forceinline__ uint32_t minbf2(uint32_t a, uint32_t b) {
    uint32_t r; asm("min.bf16x2 %0, %1, %2;" : "=r"(r) : "r"(a), "r"(b)); return r;
}
__device__ __forceinline__ uint32_t enc32(float f) {
    uint32_t u = __float_as_uint(f);
    return (u & 0x80000000u) ? ~u : (u | 0x80000000u);
}
__device__ __forceinline__ float dec32(uint32_t m) {
    uint32_t u = (m & 0x80000000u) ? (m & 0x7FFFFFFFu) : ~m;
    return __uint_as_float(u);
}

// ---------------------------------------------------------------------------
// Init 1: codebook (double trig; identical math to all passing rounds)
// ---------------------------------------------------------------------------
__global__ void vq_init() {
    __shared__ float red[64];
    const int s = blockIdx.x;
    const int d = threadIdx.x;
    const int j = d & 31;

    double expn = -((double)(2 * j) / 64.0);
    float  il   = (float)pow(100000.0, expn);
    float  pre  = __fmul_rn((float)s, il);
    float  e    = (d < 32) ? (float)sin((double)pre) : (float)cos((double)pre);

    red[d] = __fmul_rn(e, e);
    __syncthreads();
    for (int o = 32; o > 0; o >>= 1) {
        if (d < o) red[d] = __fadd_rn(red[d], red[d + o]);
        __syncthreads();
    }
    float m = __fadd_rn(__fmul_rn(red[0], (1.0f / 64.0f)), 1e-6f);
    __syncthreads();
    float r = (float)(1.0 / sqrt((double)m));
    float c = __fmul_rn(__fmul_rn(e, r), 0.35355339059327373f);

    g_cbf[s * 64 + d] = c;
    if (d == 0) g_rt[s] = __fmul_rn(r, 0.35355339059327373f);

    red[d] = __fmul_rn(c, c);
    __syncthreads();
    for (int o = 32; o > 0; o >>= 1) {
        if (d < o) red[d] = __fadd_rn(red[d], red[d + o]);
        __syncthreads();
    }
    if (d == 0) g_cn[s] = red[0];
}

// ---------------------------------------------------------------------------
// Init 2: Chebyshev tail fits + tables + CERTIFIED max-error measurement.
// Fits in fp32 (errors only inflate measured eps -> safe); truth in double
// using the exact kernel-1 formula.
// ---------------------------------------------------------------------------
__global__ void vq_init2() {
    __shared__ float scf[NSEQ][9];
    __shared__ int   seps[NSEQ];
    __shared__ float red[512];
    const int t = threadIdx.x;

    if (t < NSEQ) {
        const int jj = t >> 1, trig = t & 1;
        const int j  = JHEAD + jj;
        float w = (float)pow(100000.0, -((double)(2 * j) / 64.0));
        float c[9];
#pragma unroll
        for (int k = 0; k < 9; k++) c[k] = 0.f;
        // degree-8 Chebyshev fit, 33 nodes over [0,511]
        for (int mnode = 0; mnode < 33; mnode++) {
            float th = (float)M_PI * ((float)mnode + 0.5f) / 33.f;
            float ct = cosf(th);
            float x  = 255.5f + 255.5f * ct;
            float f  = trig ? cosf(w * x) : sinf(w * x);
            float tk0 = 1.f, tk1 = ct;
            c[0] += f; c[1] += f * ct;
#pragma unroll
            for (int k = 2; k < 9; k++) {
                float tk = 2.f * ct * tk1 - tk0;
                c[k] += f * tk;
                tk0 = tk1; tk1 = tk;
            }
        }
#pragma unroll
        for (int k = 0; k < 9; k++) c[k] *= (2.f / 33.f);
        c[0] *= 0.5f;
#pragma unroll
        for (int k = 0; k < 9; k++) { scf[t][k] = c[k]; g_cf[t * 9 + k] = c[k]; }
        seps[t] = 0;
    }
    __syncthreads();

    const int s = t;             // 512 threads, one code each
    const float rt = g_rt[s];
    // Chebyshev basis at integer s (double recurrence)
    double y = ((double)s - 255.5) / 255.5;
    double T[9];
    T[0] = 1.0; T[1] = y;
#pragma unroll
    for (int k = 2; k < 9; k++) T[k] = 2.0 * y * T[k - 1] - T[k - 2];

    // tables
#pragma unroll
    for (int k = 0; k < 9; k++) g_PT[s * PTS + k] = (float)((double)rt * T[k]);
    g_PT[s * PTS + 9]  = g_cn[s];
    g_PT[s * PTS + 10] = 0.f;
    g_PT[s * PTS + 11] = 0.f;
#pragma unroll
    for (int j = 0; j < JHEAD; j++) {
        g_HT[s * HTS + 2 * j]     = g_cbf[s * 64 + j];        // sin dim
        g_HT[s * HTS + 2 * j + 1] = g_cbf[s * 64 + 32 + j];   // cos dim
    }
#pragma unroll
    for (int p = 2 * JHEAD; p < HTS; p++) g_HT[s * HTS + p] = 0.f;

    // certified eps: truth computed EXACTLY like kernel 1
    for (int q = 0; q < NSEQ; q++) {
        const int jj = q >> 1, trig = q & 1;
        const int j  = JHEAD + jj;
        double expn = -((double)(2 * j) / 64.0);
        float  il   = (float)pow(100000.0, expn);
        float  pre  = __fmul_rn((float)s, il);
        double truth = trig ? cos((double)pre) : sin((double)pre);
        double fit = 0.0;
#pragma unroll
        for (int k = 0; k < 9; k++) fit += (double)scf[q][k] * T[k];
        float err = (float)fabs(truth - fit);
        atomicMax(&seps[q], __float_as_int(err));   // positive floats: int order ok
    }

    // r~max reduction
    red[t] = rt;
    __syncthreads();
    for (int o = 256; o > 0; o >>= 1) {
        if (t < o) red[t] = fmaxf(red[t], red[t + o]);
        __syncthreads();
    }
    if (t < NSEQ) g_E[t] = __int_as_float(seps[t]) * red[0];
}

// ---------------------------------------------------------------------------
__device__ __forceinline__ void refine(const float* __restrict__ vecs,
                                       int vglob, int row, int code,
                                       float vn, const float* spt, ull* skey) {
    const float4* vp = (const float4*)(vecs + ((size_t)vglob) * 64);
    const float4* cp = (const float4*)(g_cbf + (size_t)code * 64);
    float dot = 0.f;
#pragma unroll
    for (int kk = 0; kk < 16; kk++) {
        float4 a = vp[kk], b = cp[kk];
        dot = fmaf(a.x, b.x, dot);
        dot = fmaf(a.y, b.y, dot);
        dot = fmaf(a.z, b.z, dot);
        dot = fmaf(a.w, b.w, dot);
    }
    float dist = __fadd_rn(fmaf(-2.f, dot, vn), spt[code * PTS + 9]);
    ull key = ((ull)enc32(dist) << 9) | (uint32_t)code;
    atomicMin(&skey[row], key);
}

// ---------------------------------------------------------------------------
__global__ void __launch_bounds__(NTHR, 1) vq_main(const float* __restrict__ vecs,
                                                   const float* __restrict__ mask,
                                                   float* __restrict__ out) {
    extern __shared__ unsigned char smem[];
    float*    sht  = (float*)(smem + SHT);
    float*    spt  = (float*)(smem + SPT);
    uint32_t* smin = (uint32_t*)(smem + SMIN);
    ull*      skey = (ull*)(smem + SKEY);
    float*    sred = (float*)(smem + SRED);

    const int t   = threadIdx.x;
    const int row = t >> 2;
    const int seg = t & 3;

    // ---- copy tables into smem ----
    {
        float4* d4 = (float4*)sht;
        const float4* s4 = (const float4*)g_HT;
        for (int i = t; i < (NCODE * HTS) / 4; i += NTHR) d4[i] = s4[i];
        float4* p4 = (float4*)spt;
        const float4* q4 = (const float4*)g_PT;
        for (int i = t; i < (NCODE * PTS) / 4; i += NTHR) p4[i] = q4[i];
    }
    __syncthreads();

    float lacc = 0.f;

    for (int tile = blockIdx.x; tile < NTILE; tile += NBLK) {
        const int vbase = tile * 128;
        const int vglob = vbase + row;

        // ---- load row, exact vn, head regs, beta, certified margin ----
        float vr[64];
        {
            const float4* vp = (const float4*)(vecs + ((size_t)vglob) * 64);
#pragma unroll
            for (int i = 0; i < 16; i++) {
                float4 x = vp[i];
                vr[4 * i] = x.x; vr[4 * i + 1] = x.y;
                vr[4 * i + 2] = x.z; vr[4 * i + 3] = x.w;
            }
        }
        float vn = 0.f;
#pragma unroll
        for (int d = 0; d < 64; d++) vn = __fadd_rn(vn, __fmul_rn(vr[d], vr[d]));

        float beta[9];
#pragma unroll
        for (int k = 0; k < 9; k++) beta[k] = 0.f;
        float errb = 0.f;
#pragma unroll
        for (int jj = 0; jj < 32 - JHEAD; jj++) {
            const float av = vr[JHEAD + jj];
            const float bv = vr[32 + JHEAD + jj];
            const float* ca = g_cf + (2 * jj) * 9;
            const float* cb = g_cf + (2 * jj + 1) * 9;
#pragma unroll
            for (int k = 0; k < 9; k++)
                beta[k] = fmaf(av, ca[k], fmaf(bv, cb[k], beta[k]));
            errb = fmaf(fabsf(av), g_E[2 * jj], fmaf(fabsf(bv), g_E[2 * jj + 1], errb));
        }
        const float margin = fmaf(4.f, errb, 0.30f);

        float va[2 * JHEAD];
#pragma unroll
        for (int j = 0; j < JHEAD; j++) { va[2 * j] = vr[j]; va[2 * j + 1] = vr[32 + j]; }

        if (t < 128) { smin[t] = 0xFFFFFFFFu; skey[t] = ~0ull; }
        __syncthreads();

        // ---- scan: this thread covers codes seg+4k, k=0..127 ----
        float localmin = 3.4e38f;
        float prevw = 0.f;
        uint32_t* dbuf = (uint32_t*)(smem + SDIST + t * DSTRIDE);
#pragma unroll 2
        for (int k = 0; k < 128; k++) {
            const int code = 4 * k + seg;
            const float4* hp = (const float4*)(sht + code * HTS);
            const float4* pp = (const float4*)(spt + code * PTS);
            float4 h0 = hp[0], h1 = hp[1], h2 = hp[2];
            float4 h3 = hp[3], h4 = hp[4], h5 = hp[5];
            float acc = 0.f;
            acc = fmaf(va[0],  h0.x, acc); acc = fmaf(va[1],  h0.y, acc);
            acc = fmaf(va[2],  h0.z, acc); acc = fmaf(va[3],  h0.w, acc);
            acc = fmaf(va[4],  h1.x, acc); acc = fmaf(va[5],  h1.y, acc);
            acc = fmaf(va[6],  h1.z, acc); acc = fmaf(va[7],  h1.w, acc);
            acc = fmaf(va[8],  h2.x, acc); acc = fmaf(va[9],  h2.y, acc);
            acc = fmaf(va[10], h2.z, acc); acc = fmaf(va[11], h2.w, acc);
            acc = fmaf(va[12], h3.x, acc); acc = fmaf(va[13], h3.y, acc);
            acc = fmaf(va[14], h3.z, acc); acc = fmaf(va[15], h3.w, acc);
            acc = fmaf(va[16], h4.x, acc); acc = fmaf(va[17], h4.y, acc);
            acc = fmaf(va[18], h4.z, acc); acc = fmaf(va[19], h4.w, acc);
            acc = fmaf(va[20], h5.x, acc); acc = fmaf(va[21], h5.y, acc);
            acc = fmaf(va[22], h5.z, acc); acc = fmaf(va[23], h5.w, acc);
            float4 p0 = pp[0], p1 = pp[1], p2 = pp[2];
            acc = fmaf(beta[0], p0.x, acc); acc = fmaf(beta[1], p0.y, acc);
            acc = fmaf(beta[2], p0.z, acc); acc = fmaf(beta[3], p0.w, acc);
            acc = fmaf(beta[4], p1.x, acc); acc = fmaf(beta[5], p1.y, acc);
            acc = fmaf(beta[6], p1.z, acc); acc = fmaf(beta[7], p1.w, acc);
            acc = fmaf(beta[8], p2.x, acc);
            float w = fmaf(-2.f, acc, p2.y);        // w = cn - 2*dot~ ; dist = vn + w
            localmin = fminf(localmin, w);
            if (k & 1) dbuf[k >> 1] = bf2(prevw, w);
            else       prevw = w;
        }
        atomicMin(&smin[row], enc32(localmin));
        __syncthreads();

        // ---- threshold scan + exact fp32 refine ----
        {
            const float thr = dec32(smin[row]) + margin;
            const uint4* db = (const uint4*)(smem + SDIST + t * DSTRIDE);
#pragma unroll 1
            for (int i = 0; i < 16; i++) {
                uint4 w4 = db[i];
                uint32_t mm = minbf2(minbf2(w4.x, w4.y), minbf2(w4.z, w4.w));
                float f1 = __uint_as_float(mm << 16);
                float f2 = __uint_as_float(mm & 0xFFFF0000u);
                if (fminf(f1, f2) < thr) {
                    uint32_t ws[4] = {w4.x, w4.y, w4.z, w4.w};
#pragma unroll
                    for (int m = 0; m < 4; m++) {
                        float flo = __uint_as_float(ws[m] << 16);
                        float fhi = __uint_as_float(ws[m] & 0xFFFF0000u);
                        if (flo < thr)
                            refine(vecs, vglob, row, 4 * (8 * i + 2 * m) + seg, vn, spt, skey);
                        if (fhi < thr)
                            refine(vecs, vglob, row, 4 * (8 * i + 2 * m + 1) + seg, vn, spt, skey);
                    }
                }
            }
        }
        __syncthreads();

        // ---- outputs ----
        if (t < 128) {
            ull key = skey[t];
            int s = (int)(key & 511);
            float dist = dec32((uint32_t)(key >> 9));
            float er = fmaxf(dist, 0.f);
            int v = vbase + t;
            out[ZOFF + v] = (float)s;
            out[EOFF + v] = er;
            lacc = __fadd_rn(lacc, __fmul_rn(mask[v], er));
        }
        {
            int s = (int)(skey[row] & 511);
            const float4* cp = (const float4*)(g_cbf + (size_t)s * 64 + seg * 16);
            float4* dst = (float4*)(out + ((size_t)vglob) * 64 + seg * 16);
            dst[0] = cp[0]; dst[1] = cp[1]; dst[2] = cp[2]; dst[3] = cp[3];
        }
        __syncthreads();
    }

    // ---- l_commit block partial ----
    sred[t] = lacc;
    __syncthreads();
    for (int o = NTHR / 2; o > 0; o >>= 1) {
        if (t < o) sred[t] = __fadd_rn(sred[t], sred[t + o]);
        __syncthreads();
    }
    if (t == 0) g_part[blockIdx.x] = sred[0];
}

// ---------------------------------------------------------------------------
__global__ void vq_final(float* __restrict__ out) {
    __shared__ float s[256];
    int t = threadIdx.x;
    s[t] = (t < NBLK) ? g_part[t] : 0.f;
    __syncthreads();
    for (int o = 128; o > 0; o >>= 1) {
        if (t < o) s[t] = __fadd_rn(s[t], s[t + o]);
        __syncthreads();
    }
    if (t == 0) out[LOFF] = __fmul_rn(s[0], (1.0f / 131072.0f));
}

// ---------------------------------------------------------------------------
extern "C" void kernel_launch(void* const* d_in, const int* in_sizes, int n_in,
                              void* d_out, int out_size) {
    (void)in_sizes; (void)n_in; (void)out_size;
    const float* vecs = (const float*)d_in[0];
    const float* mask = (const float*)d_in[1];
    float* out = (float*)d_out;

    cudaFuncSetAttribute(vq_main, cudaFuncAttributeMaxDynamicSharedMemorySize, SMEM_BYTES);

    vq_init<<<NCODE, 64>>>();
    vq_init2<<<1, 512>>>();
    vq_main<<<NBLK, NTHR, SMEM_BYTES>>>(vecs, mask, out);
    vq_final<<<1, 256>>>(out);
}

// round 10
// speedup vs baseline: 1.1335x; 1.0681x over previous
#include <cuda_runtime.h>
#include <math.h>
#include <stdint.h>

// ---------------------------------------------------------------------------
// SimpleVQ: B=32, H=1, L=4096, D=64, S=512
// out (f32): quantized[NVEC*64] | z[NVEC] | l_commit | errs2[NVEC]
// Exact-head (24 dims) + certified degree-8 Chebyshev tail (9 MACs) fp32 scan
// -> measured-margin exact fp32 refine. Register-disciplined (no spills).
// ---------------------------------------------------------------------------

typedef unsigned long long ull;

#define NVEC   131072
#define NCODE  512
#define ZOFF   8388608
#define LOFF   8519680
#define EOFF   8519681
#define NBLK   148
#define NTHR   512
#define NTILE  1024

#define JHEAD  12
#define NSEQ   40
#define HTS    28              // head table row stride (floats)
#define PTS    12              // poly table row stride (floats)
#define DSTRIDE 272            // per-thread bf16 w-buffer stride (bytes)

// ---- smem layout (bytes) ---------------------------------------------------
#define SHT    0               // head table [512][28] f32      57344
#define SPT    57344           // poly table [512][12] f32      24576
#define SDIST  81920           // bf16 w-bufs / beta partials  139264
#define SMIN   221184          // u32 per-row approx min          512
#define SKEY   221696          // ull[128]                       1024
#define SRED   222720          // float[512]                     2048
#define SCF    224768          // f32 coef [40][9]               1440
#define SGE    226208          // f32 E [40]                      160
#define SMEM_BYTES 226368

__device__ float g_cbf[512 * 64];
__device__ float g_cn[512];
__device__ float g_rt[512];
__device__ float g_HT[512 * HTS];
__device__ float g_PT[512 * PTS];
__device__ float g_cf[NSEQ * 9];
__device__ float g_E[NSEQ];
__device__ float g_part[NBLK];

// ---- helpers ---------------------------------------------------------------
__device__ __forceinline__ uint32_t bf2(float lo, float hi) {
    uint32_t r; asm("cvt.rn.bf16x2.f32 %0, %1, %2;" : "=r"(r) : "f"(hi), "f"(lo)); return r;
}
__device__ __forceinline__ uint32_t minbf2(uint32_t a, uint32_t b) {
    uint32_t r; asm("min.bf16x2 %0, %1, %2;" : "=r"(r) : "r"(a), "r"(b)); return r;
}
__device__ __forceinline__ uint32_t enc32(float f) {
    uint32_t u = __float_as_uint(f);
    return (u & 0x80000000u) ? ~u : (u | 0x80000000u);
}
__device__ __forceinline__ float dec32(uint32_t m) {
    uint32_t u = (m & 0x80000000u) ? (m & 0x7FFFFFFFu) : ~m;
    return __uint_as_float(u);
}

// ---------------------------------------------------------------------------
// Init 1: codebook (double trig; identical to all passing rounds)
// ---------------------------------------------------------------------------
__global__ void vq_init() {
    __shared__ float red[64];
    const int s = blockIdx.x;
    const int d = threadIdx.x;
    const int j = d & 31;

    double expn = -((double)(2 * j) / 64.0);
    float  il   = (float)pow(100000.0, expn);
    float  pre  = __fmul_rn((float)s, il);
    float  e    = (d < 32) ? (float)sin((double)pre) : (float)cos((double)pre);

    red[d] = __fmul_rn(e, e);
    __syncthreads();
    for (int o = 32; o > 0; o >>= 1) {
        if (d < o) red[d] = __fadd_rn(red[d], red[d + o]);
        __syncthreads();
    }
    float m = __fadd_rn(__fmul_rn(red[0], (1.0f / 64.0f)), 1e-6f);
    __syncthreads();
    float r = (float)(1.0 / sqrt((double)m));
    float c = __fmul_rn(__fmul_rn(e, r), 0.35355339059327373f);

    g_cbf[s * 64 + d] = c;
    if (d == 0) g_rt[s] = __fmul_rn(r, 0.35355339059327373f);

    red[d] = __fmul_rn(c, c);
    __syncthreads();
    for (int o = 32; o > 0; o >>= 1) {
        if (d < o) red[d] = __fadd_rn(red[d], red[d + o]);
        __syncthreads();
    }
    if (d == 0) g_cn[s] = red[0];
}

// ---------------------------------------------------------------------------
// Init 2: Chebyshev fits + tables + certified max-error (same as R9, passed)
// ---------------------------------------------------------------------------
__global__ void vq_init2() {
    __shared__ float scf[NSEQ][9];
    __shared__ int   seps[NSEQ];
    __shared__ float red[512];
    const int t = threadIdx.x;

    if (t < NSEQ) {
        const int jj = t >> 1, trig = t & 1;
        const int j  = JHEAD + jj;
        float w = (float)pow(100000.0, -((double)(2 * j) / 64.0));
        float c[9];
#pragma unroll
        for (int k = 0; k < 9; k++) c[k] = 0.f;
        for (int mnode = 0; mnode < 33; mnode++) {
            float th = (float)M_PI * ((float)mnode + 0.5f) / 33.f;
            float ct = cosf(th);
            float x  = 255.5f + 255.5f * ct;
            float f  = trig ? cosf(w * x) : sinf(w * x);
            float tk0 = 1.f, tk1 = ct;
            c[0] += f; c[1] += f * ct;
#pragma unroll
            for (int k = 2; k < 9; k++) {
                float tk = 2.f * ct * tk1 - tk0;
                c[k] += f * tk;
                tk0 = tk1; tk1 = tk;
            }
        }
#pragma unroll
        for (int k = 0; k < 9; k++) c[k] *= (2.f / 33.f);
        c[0] *= 0.5f;
#pragma unroll
        for (int k = 0; k < 9; k++) { scf[t][k] = c[k]; g_cf[t * 9 + k] = c[k]; }
        seps[t] = 0;
    }
    __syncthreads();

    const int s = t;
    const float rt = g_rt[s];
    double y = ((double)s - 255.5) / 255.5;
    double T[9];
    T[0] = 1.0; T[1] = y;
#pragma unroll
    for (int k = 2; k < 9; k++) T[k] = 2.0 * y * T[k - 1] - T[k - 2];

#pragma unroll
    for (int k = 0; k < 9; k++) g_PT[s * PTS + k] = (float)((double)rt * T[k]);
    g_PT[s * PTS + 9]  = g_cn[s];
    g_PT[s * PTS + 10] = 0.f;
    g_PT[s * PTS + 11] = 0.f;
#pragma unroll
    for (int j = 0; j < JHEAD; j++) {
        g_HT[s * HTS + 2 * j]     = g_cbf[s * 64 + j];
        g_HT[s * HTS + 2 * j + 1] = g_cbf[s * 64 + 32 + j];
    }
#pragma unroll
    for (int p = 2 * JHEAD; p < HTS; p++) g_HT[s * HTS + p] = 0.f;

    for (int q = 0; q < NSEQ; q++) {
        const int jj = q >> 1, trig = q & 1;
        const int j  = JHEAD + jj;
        double expn = -((double)(2 * j) / 64.0);
        float  il   = (float)pow(100000.0, expn);
        float  pre  = __fmul_rn((float)s, il);
        double truth = trig ? cos((double)pre) : sin((double)pre);
        double fit = 0.0;
#pragma unroll
        for (int k = 0; k < 9; k++) fit += (double)scf[q][k] * T[k];
        float err = (float)fabs(truth - fit);
        atomicMax(&seps[q], __float_as_int(err));
    }

    red[t] = rt;
    __syncthreads();
    for (int o = 256; o > 0; o >>= 1) {
        if (t < o) red[t] = fmaxf(red[t], red[t + o]);
        __syncthreads();
    }
    if (t < NSEQ) g_E[t] = __int_as_float(seps[t]) * red[0];
}

// ---------------------------------------------------------------------------
__device__ __forceinline__ void refine(const float* __restrict__ vecs,
                                       int vglob, int row, int code,
                                       float vn, const float* spt, ull* skey) {
    const float4* vp = (const float4*)(vecs + ((size_t)vglob) * 64);
    const float4* cp = (const float4*)(g_cbf + (size_t)code * 64);
    float dot = 0.f;
#pragma unroll
    for (int kk = 0; kk < 16; kk++) {
        float4 a = vp[kk], b = cp[kk];
        dot = fmaf(a.x, b.x, dot);
        dot = fmaf(a.y, b.y, dot);
        dot = fmaf(a.z, b.z, dot);
        dot = fmaf(a.w, b.w, dot);
    }
    float dist = __fadd_rn(fmaf(-2.f, dot, vn), spt[code * PTS + 9]);
    ull key = ((ull)enc32(dist) << 9) | (uint32_t)code;
    atomicMin(&skey[row], key);
}

// ---------------------------------------------------------------------------
__global__ void __launch_bounds__(NTHR, 1) vq_main(const float* __restrict__ vecs,
                                                   const float* __restrict__ mask,
                                                   float* __restrict__ out) {
    extern __shared__ unsigned char smem[];
    float*    sht  = (float*)(smem + SHT);
    float*    spt  = (float*)(smem + SPT);
    uint32_t* smin = (uint32_t*)(smem + SMIN);
    ull*      skey = (ull*)(smem + SKEY);
    float*    sred = (float*)(smem + SRED);
    float*    scf  = (float*)(smem + SCF);
    float*    sge  = (float*)(smem + SGE);
    float*    bpar = (float*)(smem + SDIST);   // beta partials [128][4][12]

    const int t   = threadIdx.x;
    const int seg = t >> 7;          // warp-uniform: 0..3
    const int row = t & 127;

    // ---- copy tables into smem ----
    {
        float4* d4 = (float4*)sht;
        const float4* s4 = (const float4*)g_HT;
        for (int i = t; i < (NCODE * HTS) / 4; i += NTHR) d4[i] = s4[i];
        float4* p4 = (float4*)spt;
        const float4* q4 = (const float4*)g_PT;
        for (int i = t; i < (NCODE * PTS) / 4; i += NTHR) p4[i] = q4[i];
        for (int i = t; i < NSEQ * 9; i += NTHR) scf[i] = g_cf[i];
        if (t < NSEQ) sge[t] = g_E[t];
    }
    __syncthreads();

    float lacc = 0.f;

    for (int tile = blockIdx.x; tile < NTILE; tile += NBLK) {
        const int vbase = tile * 128;
        const int vglob = vbase + row;
        const float* vrow = vecs + ((size_t)vglob) * 64;

        // ---- beta partial over this seg's 10 tail dims ----
        {
            float bp[9];
#pragma unroll
            for (int k = 0; k < 9; k++) bp[k] = 0.f;
            float be = 0.f;
            const int idx0 = seg * 10;
#pragma unroll
            for (int u = 0; u < 10; u++) {
                const int idx = idx0 + u;
                const int q   = (idx < 20) ? (2 * idx) : (2 * (idx - 20) + 1);
                const int d   = (idx < 20) ? (12 + idx) : (44 + (idx - 20));
                const float v = vrow[d];
                const float* cfp = scf + q * 9;
#pragma unroll
                for (int k = 0; k < 9; k++) bp[k] = fmaf(v, cfp[k], bp[k]);
                be = fmaf(fabsf(v), sge[q], be);
            }
            float* w = bpar + (row * 4 + seg) * 12;
#pragma unroll
            for (int k = 0; k < 9; k++) w[k] = bp[k];
            w[9] = be;
        }

        // ---- stream row: exact ascending vn + head capture ----
        float va[2 * JHEAD];
        float vn = 0.f;
        {
            const float4* vp = (const float4*)vrow;
#pragma unroll
            for (int i = 0; i < 16; i++) {
                float4 x = vp[i];
                vn = __fadd_rn(vn, __fmul_rn(x.x, x.x));
                vn = __fadd_rn(vn, __fmul_rn(x.y, x.y));
                vn = __fadd_rn(vn, __fmul_rn(x.z, x.z));
                vn = __fadd_rn(vn, __fmul_rn(x.w, x.w));
                if (i < 3) {           // dims 0..11: sin head
                    va[2 * (4 * i) + 0] = x.x; va[2 * (4 * i + 1) + 0] = x.y;
                    va[2 * (4 * i + 2) + 0] = x.z; va[2 * (4 * i + 3) + 0] = x.w;
                } else if (i >= 8 && i < 11) {   // dims 32..43: cos head
                    const int j = 4 * (i - 8);
                    va[2 * j + 1] = x.x; va[2 * (j + 1) + 1] = x.y;
                    va[2 * (j + 2) + 1] = x.z; va[2 * (j + 3) + 1] = x.w;
                }
            }
        }
        if (t < 128) { smin[t] = 0xFFFFFFFFu; skey[t] = ~0ull; }
        __syncthreads();

        // ---- gather beta (deterministic seg order) ----
        float beta[9], errb;
        {
            const float* b0 = bpar + (row * 4 + 0) * 12;
            const float* b1 = bpar + (row * 4 + 1) * 12;
            const float* b2 = bpar + (row * 4 + 2) * 12;
            const float* b3 = bpar + (row * 4 + 3) * 12;
#pragma unroll
            for (int k = 0; k < 9; k++)
                beta[k] = __fadd_rn(__fadd_rn(b0[k], b1[k]), __fadd_rn(b2[k], b3[k]));
            errb = __fadd_rn(__fadd_rn(b0[9], b1[9]), __fadd_rn(b2[9], b3[9]));
        }
        const float margin = fmaf(4.f, errb, 0.30f);
        __syncthreads();   // partials consumed before dbuf overwrites region

        // ---- scan: this thread covers codes seg*128 + k, k=0..127 ----
        float localmin = 3.4e38f;
        float prevw = 0.f;
        uint32_t* dbuf = (uint32_t*)(smem + SDIST + t * DSTRIDE);
        const int cbase = seg * 128;
#pragma unroll 2
        for (int k = 0; k < 128; k++) {
            const int code = cbase + k;
            const float4* hp = (const float4*)(sht + code * HTS);
            const float4* pp = (const float4*)(spt + code * PTS);
            float4 h0 = hp[0], h1 = hp[1], h2 = hp[2];
            float4 h3 = hp[3], h4 = hp[4], h5 = hp[5];
            float acc = 0.f, ac2 = 0.f;
            acc = fmaf(va[0],  h0.x, acc); ac2 = fmaf(va[1],  h0.y, ac2);
            acc = fmaf(va[2],  h0.z, acc); ac2 = fmaf(va[3],  h0.w, ac2);
            acc = fmaf(va[4],  h1.x, acc); ac2 = fmaf(va[5],  h1.y, ac2);
            acc = fmaf(va[6],  h1.z, acc); ac2 = fmaf(va[7],  h1.w, ac2);
            acc = fmaf(va[8],  h2.x, acc); ac2 = fmaf(va[9],  h2.y, ac2);
            acc = fmaf(va[10], h2.z, acc); ac2 = fmaf(va[11], h2.w, ac2);
            acc = fmaf(va[12], h3.x, acc); ac2 = fmaf(va[13], h3.y, ac2);
            acc = fmaf(va[14], h3.z, acc); ac2 = fmaf(va[15], h3.w, ac2);
            acc = fmaf(va[16], h4.x, acc); ac2 = fmaf(va[17], h4.y, ac2);
            acc = fmaf(va[18], h4.z, acc); ac2 = fmaf(va[19], h4.w, ac2);
            acc = fmaf(va[20], h5.x, acc); ac2 = fmaf(va[21], h5.y, ac2);
            acc = fmaf(va[22], h5.z, acc); ac2 = fmaf(va[23], h5.w, ac2);
            float4 p0 = pp[0], p1 = pp[1], p2 = pp[2];
            acc = fmaf(beta[0], p0.x, acc); ac2 = fmaf(beta[1], p0.y, ac2);
            acc = fmaf(beta[2], p0.z, acc); ac2 = fmaf(beta[3], p0.w, ac2);
            acc = fmaf(beta[4], p1.x, acc); ac2 = fmaf(beta[5], p1.y, ac2);
            acc = fmaf(beta[6], p1.z, acc); ac2 = fmaf(beta[7], p1.w, ac2);
            acc = fmaf(beta[8], p2.x, acc);
            float w = fmaf(-2.f, acc + ac2, p2.y);   // w = cn - 2*dot~
            localmin = fminf(localmin, w);
            if (k & 1) dbuf[k >> 1] = bf2(prevw, w);
            else       prevw = w;
        }
        atomicMin(&smin[row], enc32(localmin));
        __syncthreads();

        // ---- threshold scan + exact fp32 refine ----
        {
            const float thr = dec32(smin[row]) + margin;
            const uint4* db = (const uint4*)(smem + SDIST + t * DSTRIDE);
#pragma unroll 1
            for (int i = 0; i < 16; i++) {
                uint4 w4 = db[i];
                uint32_t mm = minbf2(minbf2(w4.x, w4.y), minbf2(w4.z, w4.w));
                float f1 = __uint_as_float(mm << 16);
                float f2 = __uint_as_float(mm & 0xFFFF0000u);
                if (fminf(f1, f2) < thr) {
                    uint32_t ws[4] = {w4.x, w4.y, w4.z, w4.w};
#pragma unroll
                    for (int m = 0; m < 4; m++) {
                        float flo = __uint_as_float(ws[m] << 16);
                        float fhi = __uint_as_float(ws[m] & 0xFFFF0000u);
                        if (flo < thr)
                            refine(vecs, vglob, row, cbase + 8 * i + 2 * m, vn, spt, skey);
                        if (fhi < thr)
                            refine(vecs, vglob, row, cbase + 8 * i + 2 * m + 1, vn, spt, skey);
                    }
                }
            }
        }
        __syncthreads();

        // ---- outputs ----
        if (t < 128) {
            ull key = skey[t];
            int s = (int)(key & 511);
            float dist = dec32((uint32_t)(key >> 9));
            float er = fmaxf(dist, 0.f);
            int v = vbase + t;
            out[ZOFF + v] = (float)s;
            out[EOFF + v] = er;
            lacc = __fadd_rn(lacc, __fmul_rn(mask[v], er));
        }
        {
            int s = (int)(skey[row] & 511);
            const float4* cp = (const float4*)(g_cbf + (size_t)s * 64 + seg * 16);
            float4* dst = (float4*)(out + ((size_t)vglob) * 64 + seg * 16);
            dst[0] = cp[0]; dst[1] = cp[1]; dst[2] = cp[2]; dst[3] = cp[3];
        }
        __syncthreads();
    }

    // ---- l_commit block partial ----
    sred[t] = lacc;
    __syncthreads();
    for (int o = NTHR / 2; o > 0; o >>= 1) {
        if (t < o) sred[t] = __fadd_rn(sred[t], sred[t + o]);
        __syncthreads();
    }
    if (t == 0) g_part[blockIdx.x] = sred[0];
}

// ---------------------------------------------------------------------------
__global__ void vq_final(float* __restrict__ out) {
    __shared__ float s[256];
    int t = threadIdx.x;
    s[t] = (t < NBLK) ? g_part[t] : 0.f;
    __syncthreads();
    for (int o = 128; o > 0; o >>= 1) {
        if (t < o) s[t] = __fadd_rn(s[t], s[t + o]);
        __syncthreads();
    }
    if (t == 0) out[LOFF] = __fmul_rn(s[0], (1.0f / 131072.0f));
}

// ---------------------------------------------------------------------------
extern "C" void kernel_launch(void* const* d_in, const int* in_sizes, int n_in,
                              void* d_out, int out_size) {
    (void)in_sizes; (void)n_in; (void)out_size;
    const float* vecs = (const float*)d_in[0];
    const float* mask = (const float*)d_in[1];
    float* out = (float*)d_out;

    cudaFuncSetAttribute(vq_main, cudaFuncAttributeMaxDynamicSharedMemorySize, SMEM_BYTES);

    vq_init<<<NCODE, 64>>>();
    vq_init2<<<1, 512>>>();
    vq_main<<<NBLK, NTHR, SMEM_BYTES>>>(vecs, mask, out);
    vq_final<<<1, 256>>>(out);
}